// round 12
// baseline (speedup 1.0000x reference)
#include <cuda_runtime.h>
#include <cuda_fp16.h>
#include <math.h>

#define TT   5
#define CC   2
#define NN   4096
#define EE   150000
#define WIN  512
#define WOUT 128
#define NT   1024
#define NCLS 16
#define NEDGES (TT * EE)        // 750000
#define CNT_BLOCKS 367          // ceil(750000 / 2048), 8 edges/thread
#define SCT_BLOCKS 733          // ceil(750000 / 1024), 4 edges/thread

// ---------------- static scratch ----------------
__device__ int   g_cnt[TT * NN];               // zeroed by scan_k after use (replay-safe)
__device__ int   g_rowptr[TT * (NN + 1)];
__device__ int   g_rank[NEDGES];
__device__ __align__(16) int2 g_edge[NEDGES];  // {dst, val_bits}
__device__ float g_f1[CC * TT], g_f2[CC * TT], g_f3[CC * TT];
__device__ __align__(8)  float2 g_t3[NN];      // {t3_c0, t3_c1}
__device__ __align__(16) float4 g_s2u[NN];     // {s2_c0, s2_c1, u_c0, u_c1}
__device__ __align__(16) float  g_XW[NN * WOUT];        // fp32 payload for stageA
__device__ __align__(16) __half g_Y3h[NN * 2 * WOUT];   // [node][lane][ch0 x4, ch1 x4]
__device__ __align__(16) __half g_Y2h[NN * 2 * WOUT];

struct __align__(16) H8 { __half2 a, b, c, d; };

// ---------------- launch 1: gemm (blocks 0..127) + count+rank (128..494) + softmax (495) ----------------
__global__ void __launch_bounds__(256) prep_count_k(const int* __restrict__ edge_index,
                                                    const float* __restrict__ X,
                                                    const float* __restrict__ Wt,
                                                    const float* __restrict__ w1,
                                                    const float* __restrict__ w2,
                                                    const float* __restrict__ w3) {
    int b = blockIdx.x;
    int tid = threadIdx.x;
    if (b < 128) {
        __shared__ float Xs[32][36];     // padded, 16B-aligned rows
        __shared__ float Ws[32][WOUT];
        int cx = tid & 31;
        int cy = tid >> 5;
        int row0 = b * 32;
        float acc[4][4];
#pragma unroll
        for (int i = 0; i < 4; i++)
#pragma unroll
            for (int k = 0; k < 4; k++) acc[i][k] = 0.f;
        for (int k0 = 0; k0 < WIN; k0 += 32) {
            {
                int r = tid >> 3, c4 = tid & 7;
                float4 xv4 = *(const float4*)&X[(row0 + r) * WIN + k0 + c4 * 4];
                *(float4*)&Xs[r][c4 * 4] = xv4;
            }
#pragma unroll
            for (int i = 0; i < 4; i++) {
                int li = tid + i * 256;
                int r = li >> 5, c4 = li & 31;
                *(float4*)&Ws[r][c4 * 4] = *(const float4*)&Wt[(k0 + r) * WOUT + c4 * 4];
            }
            __syncthreads();
#pragma unroll
            for (int kk = 0; kk < 32; kk++) {
                float xv[4];
#pragma unroll
                for (int i = 0; i < 4; i++) xv[i] = Xs[cy * 4 + i][kk];
                float4 wv = *(float4*)&Ws[kk][cx * 4];
#pragma unroll
                for (int i = 0; i < 4; i++) {
                    acc[i][0] += xv[i] * wv.x;
                    acc[i][1] += xv[i] * wv.y;
                    acc[i][2] += xv[i] * wv.z;
                    acc[i][3] += xv[i] * wv.w;
                }
            }
            __syncthreads();
        }
#pragma unroll
        for (int i = 0; i < 4; i++) {
            float4 o = make_float4(acc[i][0], acc[i][1], acc[i][2], acc[i][3]);
            *(float4*)&g_XW[(row0 + cy * 4 + i) * WOUT + cx * 4] = o;
        }
    } else if (b < 128 + CNT_BLOCKS) {
        int base = (b - 128) * 2048;
#pragma unroll
        for (int i = 0; i < 8; i++) {
            int idx = base + i * 256 + tid;
            if (idx < NEDGES) {
                int j = idx / EE, e = idx - j * EE;
                int src = edge_index[j * 2 * EE + e];
                int r = atomicAdd(&g_cnt[j * NN + src], 1);
                g_rank[idx] = r;
            }
        }
    } else {
        if (tid < 6) {
            int m = tid >> 1, c = tid & 1;
            const float* w = (m == 0 ? w1 : (m == 1 ? w2 : w3)) + c * TT;
            float*       f = (m == 0 ? g_f1 : (m == 1 ? g_f2 : g_f3)) + c * TT;
            float mx = w[0];
            for (int j = 1; j < TT; j++) mx = fmaxf(mx, w[j]);
            float e[TT], s = 0.f;
            for (int j = 0; j < TT; j++) { e[j] = expf(w[j] - mx); s += e[j]; }
            float inv = 1.f / s;
            for (int j = 0; j < TT; j++) f[j] = e[j] * inv;
        }
    }
}

// ---------------- launch 2: exclusive scan per type; re-zeroes g_cnt ----------------
__global__ void __launch_bounds__(256) scan_k() {
    const int R = 16;
    int j = blockIdx.x, tid = threadIdx.x;
    int base = j * NN + tid * R;
    int v[R];
    int s = 0;
#pragma unroll
    for (int i = 0; i < R; i++) { v[i] = g_cnt[base + i]; s += v[i]; }
#pragma unroll
    for (int i = 0; i < R; i++) g_cnt[base + i] = 0;
    __shared__ int warpsum[8];
    int lane = tid & 31, w = tid >> 5;
    int pre = s;
#pragma unroll
    for (int off = 1; off < 32; off <<= 1) {
        int t = __shfl_up_sync(~0u, pre, off);
        if (lane >= off) pre += t;
    }
    if (lane == 31) warpsum[w] = pre;
    __syncthreads();
    if (w == 0) {
        int ws = (lane < 8) ? warpsum[lane] : 0;
#pragma unroll
        for (int off = 1; off < 8; off <<= 1) {
            int t = __shfl_up_sync(~0u, ws, off);
            if (lane >= off) ws += t;
        }
        if (lane < 8) warpsum[lane] = ws;
    }
    __syncthreads();
    int run = pre - s + (w > 0 ? warpsum[w - 1] : 0);
#pragma unroll
    for (int i = 0; i < R; i++) {
        g_rowptr[j * (NN + 1) + tid * R + i] = run;
        run += v[i];
    }
    if (tid == 255) g_rowptr[j * (NN + 1) + NN] = run;
}

// ---------------- launch 3: scatter into CSR, atomic-free ----------------
__global__ void __launch_bounds__(256) scatter_k(const int* __restrict__ edge_index,
                                                 const float* __restrict__ edge_value) {
    int b = blockIdx.x, tid = threadIdx.x;
    int base = b * 1024;
#pragma unroll
    for (int i = 0; i < 4; i++) {
        int idx = base + i * 256 + tid;
        if (idx < NEDGES) {
            int j = idx / EE, e = idx - j * EE;
            int src = edge_index[j * 2 * EE + e];
            int dst = edge_index[j * 2 * EE + EE + e];
            float v = edge_value[j * EE + e];
            int pos = g_rowptr[j * (NN + 1) + src] + g_rank[idx];
            g_edge[j * EE + pos] = make_int2(dst, __float_as_int(v));
        }
    }
}

// ---------------- launch 4: stageA (blocks 0..2047, 4 warps/row, 2 rows/block) + rs/s2t3 (2048..2559) ----------------
__global__ void __launch_bounds__(256) stageA_k() {
    int b = blockIdx.x;
    int tid = threadIdx.x, w = tid >> 5, lane = tid & 31;
    if (b < 2048) {
        __shared__ float4 smf[8][2][33];
        int row = b * 2 + (w >> 2);
        int q = w & 3;
        float4 a0 = make_float4(0, 0, 0, 0), a1 = make_float4(0, 0, 0, 0);
#pragma unroll
        for (int j = 0; j < TT; j++) {
            float c0 = g_f3[j], c1 = g_f3[TT + j];
            int s = g_rowptr[j * (NN + 1) + row], e = g_rowptr[j * (NN + 1) + row + 1];
            int len = e - s;
            int qs = s + ((len * q) >> 2), qe = s + ((len * (q + 1)) >> 2);
            const int2* ep = g_edge + j * EE;
            float4 P = make_float4(0, 0, 0, 0);
#pragma unroll 4
            for (int k = qs; k < qe; k++) {
                int2 ev = ep[k];
                float v = __int_as_float(ev.y);
                float4 x = *(const float4*)&g_XW[ev.x * WOUT + lane * 4];
                P.x += v * x.x; P.y += v * x.y; P.z += v * x.z; P.w += v * x.w;
            }
            a0.x += c0 * P.x; a0.y += c0 * P.y; a0.z += c0 * P.z; a0.w += c0 * P.w;
            a1.x += c1 * P.x; a1.y += c1 * P.y; a1.z += c1 * P.z; a1.w += c1 * P.w;
        }
        smf[w][0][lane] = a0;
        smf[w][1][lane] = a1;
        __syncthreads();
        if (q == 0) {
            float4 v0 = smf[w][0][lane], v1 = smf[w][1][lane];
#pragma unroll
            for (int ww = 1; ww < 4; ww++) {
                float4 q0 = smf[w + ww][0][lane], q1 = smf[w + ww][1][lane];
                v0.x += q0.x; v0.y += q0.y; v0.z += q0.z; v0.w += q0.w;
                v1.x += q1.x; v1.y += q1.y; v1.z += q1.z; v1.w += q1.w;
            }
            H8 o;
            o.a = __floats2half2_rn(v0.x, v0.y);
            o.b = __floats2half2_rn(v0.z, v0.w);
            o.c = __floats2half2_rn(v1.x, v1.y);
            o.d = __floats2half2_rn(v1.z, v1.w);
            *(H8*)&g_Y3h[row * 256 + lane * 8] = o;
        }
    } else {
        // rs -> s2 (into g_s2u.xy) and t3 (g_t3); warp per row
        int r = (b - 2048) * 8 + w;
        float s20 = 0.f, s21 = 0.f, t30 = 0.f, t31 = 0.f;
#pragma unroll
        for (int j = 0; j < TT; j++) {
            int s = g_rowptr[j * (NN + 1) + r], e = g_rowptr[j * (NN + 1) + r + 1];
            const int2* ep = g_edge + j * EE;
            float acc = 0.f;
            for (int k = s + lane; k < e; k += 32)
                acc += __int_as_float(ep[k].y);
#pragma unroll
            for (int off = 16; off > 0; off >>= 1)
                acc += __shfl_xor_sync(~0u, acc, off);
            s20 += g_f2[j] * acc;       s21 += g_f2[TT + j] * acc;
            t30 += g_f3[j] * acc;       t31 += g_f3[TT + j] * acc;
        }
        if (lane == 0) {
            g_t3[r] = make_float2(t30, t31);
            *(float2*)&g_s2u[r] = make_float2(s20, s21);   // writes .x, .y
        }
    }
}

// ---------------- launch 5: stageB (blocks 0..2047) + u (2048..2559) ----------------
__global__ void __launch_bounds__(256) stageB_k() {
    int b = blockIdx.x;
    int tid = threadIdx.x, w = tid >> 5, lane = tid & 31;
    if (b < 2048) {
        __shared__ float4 smf[8][2][33];
        int row = b * 2 + (w >> 2);
        int q = w & 3;
        float4 a0 = make_float4(0, 0, 0, 0), a1 = make_float4(0, 0, 0, 0);
#pragma unroll
        for (int j = 0; j < TT; j++) {
            float c0 = g_f2[j], c1 = g_f2[TT + j];
            int s = g_rowptr[j * (NN + 1) + row], e = g_rowptr[j * (NN + 1) + row + 1];
            int len = e - s;
            int qs = s + ((len * q) >> 2), qe = s + ((len * (q + 1)) >> 2);
            const int2* ep = g_edge + j * EE;
            float4 P0 = make_float4(0, 0, 0, 0), P1 = make_float4(0, 0, 0, 0);
#pragma unroll 4
            for (int k = qs; k < qe; k++) {
                int2 ev = ep[k];
                float v = __int_as_float(ev.y);
                H8 y = *(const H8*)&g_Y3h[ev.x * 256 + lane * 8];
                float2 y00 = __half22float2(y.a), y01 = __half22float2(y.b);
                float2 y10 = __half22float2(y.c), y11 = __half22float2(y.d);
                P0.x += v * y00.x; P0.y += v * y00.y; P0.z += v * y01.x; P0.w += v * y01.y;
                P1.x += v * y10.x; P1.y += v * y10.y; P1.z += v * y11.x; P1.w += v * y11.y;
            }
            a0.x += c0 * P0.x; a0.y += c0 * P0.y; a0.z += c0 * P0.z; a0.w += c0 * P0.w;
            a1.x += c1 * P1.x; a1.y += c1 * P1.y; a1.z += c1 * P1.z; a1.w += c1 * P1.w;
        }
        smf[w][0][lane] = a0;
        smf[w][1][lane] = a1;
        __syncthreads();
        if (q == 0) {
            float4 v0 = smf[w][0][lane], v1 = smf[w][1][lane];
#pragma unroll
            for (int ww = 1; ww < 4; ww++) {
                float4 q0 = smf[w + ww][0][lane], q1 = smf[w + ww][1][lane];
                v0.x += q0.x; v0.y += q0.y; v0.z += q0.z; v0.w += q0.w;
                v1.x += q1.x; v1.y += q1.y; v1.z += q1.z; v1.w += q1.w;
            }
            H8 o;
            o.a = __floats2half2_rn(v0.x, v0.y);
            o.b = __floats2half2_rn(v0.z, v0.w);
            o.c = __floats2half2_rn(v1.x, v1.y);
            o.d = __floats2half2_rn(v1.z, v1.w);
            *(H8*)&g_Y2h[row * 256 + lane * 8] = o;
        }
    } else {
        // u (into g_s2u.zw)
        int r = (b - 2048) * 8 + w;
        float acc0 = 0.f, acc1 = 0.f;
#pragma unroll
        for (int j = 0; j < TT; j++) {
            float f0 = g_f2[j], f1 = g_f2[TT + j];
            int s = g_rowptr[j * (NN + 1) + r], e = g_rowptr[j * (NN + 1) + r + 1];
            const int2* ep = g_edge + j * EE;
            float p0 = 0.f, p1 = 0.f;
            for (int k = s + lane; k < e; k += 32) {
                int2 ev = ep[k];
                float v = __int_as_float(ev.y);
                float2 t3 = g_t3[ev.x];
                p0 += v * t3.x;
                p1 += v * t3.y;
            }
            acc0 += f0 * p0;
            acc1 += f1 * p1;
        }
#pragma unroll
        for (int off = 16; off > 0; off >>= 1) {
            acc0 += __shfl_down_sync(~0u, acc0, off);
            acc1 += __shfl_down_sync(~0u, acc1, off);
        }
        if (lane == 0) *(float2*)((float*)&g_s2u[r] + 2) = make_float2(acc0, acc1);  // writes .z, .w
    }
}

// ---------------- launch 6: stageC + final linear. 2 targets/block, 4 warps/target ----------------
__global__ void __launch_bounds__(256) stageC_k(const int* __restrict__ target,
                                                const float* __restrict__ gcn_b,
                                                const float* __restrict__ lin_w,
                                                const float* __restrict__ lin_b,
                                                float* __restrict__ out) {
    __shared__ float4 smf[8][2][33];
    __shared__ float smd[8][4];
    __shared__ float xts[2][CC * WOUT];
    int b = blockIdx.x;
    int tid = threadIdx.x, w = tid >> 5, lane = tid & 31;
    int tloc = w >> 2, q = w & 3;
    int t = b * 2 + tloc;
    int row = target[t];
    float4 a0 = make_float4(0, 0, 0, 0), a1 = make_float4(0, 0, 0, 0);
    float d10 = 0.f, d11 = 0.f, d20 = 0.f, d21 = 0.f;
#pragma unroll
    for (int j = 0; j < TT; j++) {
        float c0 = g_f1[j], c1 = g_f1[TT + j];
        int s = g_rowptr[j * (NN + 1) + row], e = g_rowptr[j * (NN + 1) + row + 1];
        int len = e - s;
        int qs = s + ((len * q) >> 2), qe = s + ((len * (q + 1)) >> 2);
        const int2* ep = g_edge + j * EE;
        float4 P0 = make_float4(0, 0, 0, 0), P1 = make_float4(0, 0, 0, 0);
        float pd10 = 0.f, pd11 = 0.f, pd20 = 0.f, pd21 = 0.f;
#pragma unroll 4
        for (int k = qs; k < qe; k++) {
            int2 ev = ep[k];
            int d = ev.x;
            float v = __int_as_float(ev.y);
            H8 y = *(const H8*)&g_Y2h[d * 256 + lane * 8];
            float2 y00 = __half22float2(y.a), y01 = __half22float2(y.b);
            float2 y10 = __half22float2(y.c), y11 = __half22float2(y.d);
            P0.x += v * y00.x; P0.y += v * y00.y; P0.z += v * y01.x; P0.w += v * y01.y;
            P1.x += v * y10.x; P1.y += v * y10.y; P1.z += v * y11.x; P1.w += v * y11.y;
            float4 su = g_s2u[d];
            pd10 += v * su.x; pd11 += v * su.y;
            pd20 += v * su.z; pd21 += v * su.w;
        }
        a0.x += c0 * P0.x; a0.y += c0 * P0.y; a0.z += c0 * P0.z; a0.w += c0 * P0.w;
        a1.x += c1 * P1.x; a1.y += c1 * P1.y; a1.z += c1 * P1.z; a1.w += c1 * P1.w;
        d10 += c0 * pd10; d11 += c1 * pd11;
        d20 += c0 * pd20; d21 += c1 * pd21;
    }
    smf[w][0][lane] = a0;
    smf[w][1][lane] = a1;
    // degree terms are warp-uniform: lane 0's copy is the full per-warp partial.
    if (lane == 0) { smd[w][0] = d10; smd[w][1] = d11; smd[w][2] = d20; smd[w][3] = d21; }
    __syncthreads();
    if (q == 0) {
        float4 v0 = smf[w][0][lane], v1 = smf[w][1][lane];
        float D10 = smd[w][0], D11 = smd[w][1], D20 = smd[w][2], D21 = smd[w][3];
#pragma unroll
        for (int ww = 1; ww < 4; ww++) {
            float4 q0 = smf[w + ww][0][lane], q1 = smf[w + ww][1][lane];
            v0.x += q0.x; v0.y += q0.y; v0.z += q0.z; v0.w += q0.w;
            v1.x += q1.x; v1.y += q1.y; v1.z += q1.z; v1.w += q1.w;
            D10 += smd[w + ww][0]; D11 += smd[w + ww][1];
            D20 += smd[w + ww][2]; D21 += smd[w + ww][3];
        }
        float i10 = (D10 == 0.f) ? 0.f : 1.f / D10;
        float dg0 = i10 * D20;
        float i20 = (dg0 == 0.f) ? 0.f : 1.f / dg0;
        float sc0 = i10 * i20;
        float i11 = (D11 == 0.f) ? 0.f : 1.f / D11;
        float dg1 = i11 * D21;
        float i21 = (dg1 == 0.f) ? 0.f : 1.f / dg1;
        float sc1 = i11 * i21;
        float4 bb = *(const float4*)&gcn_b[lane * 4];
        xts[tloc][0 * WOUT + lane * 4 + 0] = fmaxf(sc0 * v0.x + bb.x, 0.f);
        xts[tloc][0 * WOUT + lane * 4 + 1] = fmaxf(sc0 * v0.y + bb.y, 0.f);
        xts[tloc][0 * WOUT + lane * 4 + 2] = fmaxf(sc0 * v0.z + bb.z, 0.f);
        xts[tloc][0 * WOUT + lane * 4 + 3] = fmaxf(sc0 * v0.w + bb.w, 0.f);
        xts[tloc][1 * WOUT + lane * 4 + 0] = fmaxf(sc1 * v1.x + bb.x, 0.f);
        xts[tloc][1 * WOUT + lane * 4 + 1] = fmaxf(sc1 * v1.y + bb.y, 0.f);
        xts[tloc][1 * WOUT + lane * 4 + 2] = fmaxf(sc1 * v1.z + bb.z, 0.f);
        xts[tloc][1 * WOUT + lane * 4 + 3] = fmaxf(sc1 * v1.w + bb.w, 0.f);
    }
    __syncthreads();
    if (q == 0 && lane < NCLS) {
        float acc = lin_b[lane];
#pragma unroll 8
        for (int k = 0; k < CC * WOUT; k++)
            acc += xts[tloc][k] * lin_w[k * NCLS + lane];
        out[t * NCLS + lane] = acc;
    }
}

// ---------------- launch ----------------
extern "C" void kernel_launch(void* const* d_in, const int* in_sizes, int n_in,
                              void* d_out, int out_size) {
    const int*   edge_index = (const int*)d_in[0];
    const float* edge_value = (const float*)d_in[1];
    const float* X          = (const float*)d_in[2];
    const int*   target_x   = (const int*)d_in[3];
    const float* w_l0_c1    = (const float*)d_in[4];
    const float* w_l0_c2    = (const float*)d_in[5];
    const float* w_l1_c1    = (const float*)d_in[6];
    const float* gcn_w      = (const float*)d_in[7];
    const float* gcn_b      = (const float*)d_in[8];
    const float* lin_w      = (const float*)d_in[9];
    const float* lin_b      = (const float*)d_in[10];
    float* out = (float*)d_out;

    prep_count_k<<<128 + CNT_BLOCKS + 1, 256>>>(edge_index, X, gcn_w, w_l0_c1, w_l0_c2, w_l1_c1);
    scan_k<<<TT, 256>>>();
    scatter_k<<<SCT_BLOCKS, 256>>>(edge_index, edge_value);
    stageA_k<<<2048 + 512, 256>>>();
    stageB_k<<<2048 + 512, 256>>>();
    stageC_k<<<NT / 2, 256>>>(target_x, gcn_b, lin_w, lin_b, out);
}

// round 13
// speedup vs baseline: 1.0273x; 1.0273x over previous
#include <cuda_runtime.h>
#include <cuda_fp16.h>
#include <math.h>

#define TT   5
#define CC   2
#define NN   4096
#define EE   150000
#define WIN  512
#define WOUT 128
#define NT   1024
#define NCLS 16
#define NEDGES (TT * EE)        // 750000
#define CNT_BLOCKS 367          // ceil(750000 / 2048), 8 edges/thread
#define SCT_BLOCKS 733          // ceil(750000 / 1024), 4 edges/thread

// ---------------- static scratch ----------------
__device__ int   g_cnt[TT * NN];               // zeroed by scan_k after use (replay-safe)
__device__ int   g_rowptr[TT * (NN + 1)];
__device__ int   g_rank[NEDGES];
__device__ __align__(16) int2 g_edge[NEDGES];  // {dst, val_bits}
__device__ float g_f1[CC * TT], g_f2[CC * TT], g_f3[CC * TT];
__device__ __align__(8)  float2 g_t3[NN];      // {t3_c0, t3_c1}
__device__ __align__(16) float4 g_s2u[NN];     // {s2_c0, s2_c1, u_c0, u_c1}
__device__ __align__(16) __half g_XWh[NN * WOUT];       // fp16 payload for stageA
__device__ __align__(16) __half g_Y3h[NN * 2 * WOUT];   // [node][lane][ch0 x4, ch1 x4]
__device__ __align__(16) __half g_Y2h[NN * 2 * WOUT];

struct __align__(16) H8 { __half2 a, b, c, d; };

// ---------------- launch 1: gemm (blocks 0..127) + count+rank (128..494) + softmax (495) ----------------
__global__ void __launch_bounds__(256) prep_count_k(const int* __restrict__ edge_index,
                                                    const float* __restrict__ X,
                                                    const float* __restrict__ Wt,
                                                    const float* __restrict__ w1,
                                                    const float* __restrict__ w2,
                                                    const float* __restrict__ w3) {
    int b = blockIdx.x;
    int tid = threadIdx.x;
    if (b < 128) {
        __shared__ float Xs[32][36];     // padded, 16B-aligned rows
        __shared__ float Ws[32][WOUT];
        int cx = tid & 31;
        int cy = tid >> 5;
        int row0 = b * 32;
        float acc[4][4];
#pragma unroll
        for (int i = 0; i < 4; i++)
#pragma unroll
            for (int k = 0; k < 4; k++) acc[i][k] = 0.f;
        for (int k0 = 0; k0 < WIN; k0 += 32) {
            {
                int r = tid >> 3, c4 = tid & 7;
                float4 xv4 = *(const float4*)&X[(row0 + r) * WIN + k0 + c4 * 4];
                *(float4*)&Xs[r][c4 * 4] = xv4;
            }
#pragma unroll
            for (int i = 0; i < 4; i++) {
                int li = tid + i * 256;
                int r = li >> 5, c4 = li & 31;
                *(float4*)&Ws[r][c4 * 4] = *(const float4*)&Wt[(k0 + r) * WOUT + c4 * 4];
            }
            __syncthreads();
#pragma unroll
            for (int kk = 0; kk < 32; kk++) {
                float xv[4];
#pragma unroll
                for (int i = 0; i < 4; i++) xv[i] = Xs[cy * 4 + i][kk];
                float4 wv = *(float4*)&Ws[kk][cx * 4];
#pragma unroll
                for (int i = 0; i < 4; i++) {
                    acc[i][0] += xv[i] * wv.x;
                    acc[i][1] += xv[i] * wv.y;
                    acc[i][2] += xv[i] * wv.z;
                    acc[i][3] += xv[i] * wv.w;
                }
            }
            __syncthreads();
        }
#pragma unroll
        for (int i = 0; i < 4; i++) {
            __half2 h0 = __floats2half2_rn(acc[i][0], acc[i][1]);
            __half2 h1 = __floats2half2_rn(acc[i][2], acc[i][3]);
            __half2* p = (__half2*)&g_XWh[(row0 + cy * 4 + i) * WOUT + cx * 4];
            p[0] = h0; p[1] = h1;
        }
    } else if (b < 128 + CNT_BLOCKS) {
        int base = (b - 128) * 2048;
#pragma unroll
        for (int i = 0; i < 8; i++) {
            int idx = base + i * 256 + tid;
            if (idx < NEDGES) {
                int j = idx / EE, e = idx - j * EE;
                int src = edge_index[j * 2 * EE + e];
                int r = atomicAdd(&g_cnt[j * NN + src], 1);
                g_rank[idx] = r;
            }
        }
    } else {
        if (tid < 6) {
            int m = tid >> 1, c = tid & 1;
            const float* w = (m == 0 ? w1 : (m == 1 ? w2 : w3)) + c * TT;
            float*       f = (m == 0 ? g_f1 : (m == 1 ? g_f2 : g_f3)) + c * TT;
            float mx = w[0];
            for (int j = 1; j < TT; j++) mx = fmaxf(mx, w[j]);
            float e[TT], s = 0.f;
            for (int j = 0; j < TT; j++) { e[j] = expf(w[j] - mx); s += e[j]; }
            float inv = 1.f / s;
            for (int j = 0; j < TT; j++) f[j] = e[j] * inv;
        }
    }
}

// ---------------- launch 2: exclusive scan per type; re-zeroes g_cnt ----------------
__global__ void __launch_bounds__(256) scan_k() {
    const int R = 16;
    int j = blockIdx.x, tid = threadIdx.x;
    int base = j * NN + tid * R;
    int v[R];
    int s = 0;
#pragma unroll
    for (int i = 0; i < R; i++) { v[i] = g_cnt[base + i]; s += v[i]; }
#pragma unroll
    for (int i = 0; i < R; i++) g_cnt[base + i] = 0;
    __shared__ int warpsum[8];
    int lane = tid & 31, w = tid >> 5;
    int pre = s;
#pragma unroll
    for (int off = 1; off < 32; off <<= 1) {
        int t = __shfl_up_sync(~0u, pre, off);
        if (lane >= off) pre += t;
    }
    if (lane == 31) warpsum[w] = pre;
    __syncthreads();
    if (w == 0) {
        int ws = (lane < 8) ? warpsum[lane] : 0;
#pragma unroll
        for (int off = 1; off < 8; off <<= 1) {
            int t = __shfl_up_sync(~0u, ws, off);
            if (lane >= off) ws += t;
        }
        if (lane < 8) warpsum[lane] = ws;
    }
    __syncthreads();
    int run = pre - s + (w > 0 ? warpsum[w - 1] : 0);
#pragma unroll
    for (int i = 0; i < R; i++) {
        g_rowptr[j * (NN + 1) + tid * R + i] = run;
        run += v[i];
    }
    if (tid == 255) g_rowptr[j * (NN + 1) + NN] = run;
}

// ---------------- launch 3: scatter into CSR, atomic-free ----------------
__global__ void __launch_bounds__(256) scatter_k(const int* __restrict__ edge_index,
                                                 const float* __restrict__ edge_value) {
    int b = blockIdx.x, tid = threadIdx.x;
    int base = b * 1024;
#pragma unroll
    for (int i = 0; i < 4; i++) {
        int idx = base + i * 256 + tid;
        if (idx < NEDGES) {
            int j = idx / EE, e = idx - j * EE;
            int src = edge_index[j * 2 * EE + e];
            int dst = edge_index[j * 2 * EE + EE + e];
            float v = edge_value[j * EE + e];
            int pos = g_rowptr[j * (NN + 1) + src] + g_rank[idx];
            g_edge[j * EE + pos] = make_int2(dst, __float_as_int(v));
        }
    }
}

// ---------------- launch 4: stageA (blocks 0..2047, 4 warps/row, 2 rows/block) + rs/s2t3 (2048..2559) ----------------
__global__ void __launch_bounds__(256) stageA_k() {
    int b = blockIdx.x;
    int tid = threadIdx.x, w = tid >> 5, lane = tid & 31;
    if (b < 2048) {
        __shared__ float4 smf[8][2][33];
        int row = b * 2 + (w >> 2);
        int q = w & 3;
        float4 a0 = make_float4(0, 0, 0, 0), a1 = make_float4(0, 0, 0, 0);
#pragma unroll
        for (int j = 0; j < TT; j++) {
            float c0 = g_f3[j], c1 = g_f3[TT + j];
            int s = g_rowptr[j * (NN + 1) + row], e = g_rowptr[j * (NN + 1) + row + 1];
            int len = e - s;
            int qs = s + ((len * q) >> 2), qe = s + ((len * (q + 1)) >> 2);
            const int2* ep = g_edge + j * EE;
            float4 P = make_float4(0, 0, 0, 0);
#pragma unroll 4
            for (int k = qs; k < qe; k++) {
                int2 ev = ep[k];
                float v = __int_as_float(ev.y);
                int2 raw = *(const int2*)&g_XWh[ev.x * WOUT + lane * 4];
                float2 x01 = __half22float2(*(__half2*)&raw.x);
                float2 x23 = __half22float2(*(__half2*)&raw.y);
                P.x += v * x01.x; P.y += v * x01.y; P.z += v * x23.x; P.w += v * x23.y;
            }
            a0.x += c0 * P.x; a0.y += c0 * P.y; a0.z += c0 * P.z; a0.w += c0 * P.w;
            a1.x += c1 * P.x; a1.y += c1 * P.y; a1.z += c1 * P.z; a1.w += c1 * P.w;
        }
        smf[w][0][lane] = a0;
        smf[w][1][lane] = a1;
        __syncthreads();
        if (q == 0) {
            float4 v0 = smf[w][0][lane], v1 = smf[w][1][lane];
#pragma unroll
            for (int ww = 1; ww < 4; ww++) {
                float4 q0 = smf[w + ww][0][lane], q1 = smf[w + ww][1][lane];
                v0.x += q0.x; v0.y += q0.y; v0.z += q0.z; v0.w += q0.w;
                v1.x += q1.x; v1.y += q1.y; v1.z += q1.z; v1.w += q1.w;
            }
            H8 o;
            o.a = __floats2half2_rn(v0.x, v0.y);
            o.b = __floats2half2_rn(v0.z, v0.w);
            o.c = __floats2half2_rn(v1.x, v1.y);
            o.d = __floats2half2_rn(v1.z, v1.w);
            *(H8*)&g_Y3h[row * 256 + lane * 8] = o;
        }
    } else {
        // rs -> s2 (into g_s2u.xy) and t3 (g_t3); warp per row
        int r = (b - 2048) * 8 + w;
        float s20 = 0.f, s21 = 0.f, t30 = 0.f, t31 = 0.f;
#pragma unroll
        for (int j = 0; j < TT; j++) {
            int s = g_rowptr[j * (NN + 1) + r], e = g_rowptr[j * (NN + 1) + r + 1];
            const int2* ep = g_edge + j * EE;
            float acc = 0.f;
            for (int k = s + lane; k < e; k += 32)
                acc += __int_as_float(ep[k].y);
#pragma unroll
            for (int off = 16; off > 0; off >>= 1)
                acc += __shfl_xor_sync(~0u, acc, off);
            s20 += g_f2[j] * acc;       s21 += g_f2[TT + j] * acc;
            t30 += g_f3[j] * acc;       t31 += g_f3[TT + j] * acc;
        }
        if (lane == 0) {
            g_t3[r] = make_float2(t30, t31);
            *(float2*)&g_s2u[r] = make_float2(s20, s21);   // writes .x, .y
        }
    }
}

// ---------------- launch 5: stageB (blocks 0..2047) + u (2048..2559) ----------------
__global__ void __launch_bounds__(256) stageB_k() {
    int b = blockIdx.x;
    int tid = threadIdx.x, w = tid >> 5, lane = tid & 31;
    if (b < 2048) {
        __shared__ float4 smf[8][2][33];
        int row = b * 2 + (w >> 2);
        int q = w & 3;
        float4 a0 = make_float4(0, 0, 0, 0), a1 = make_float4(0, 0, 0, 0);
#pragma unroll
        for (int j = 0; j < TT; j++) {
            float c0 = g_f2[j], c1 = g_f2[TT + j];
            int s = g_rowptr[j * (NN + 1) + row], e = g_rowptr[j * (NN + 1) + row + 1];
            int len = e - s;
            int qs = s + ((len * q) >> 2), qe = s + ((len * (q + 1)) >> 2);
            const int2* ep = g_edge + j * EE;
            float4 P0 = make_float4(0, 0, 0, 0), P1 = make_float4(0, 0, 0, 0);
#pragma unroll 4
            for (int k = qs; k < qe; k++) {
                int2 ev = ep[k];
                float v = __int_as_float(ev.y);
                H8 y = *(const H8*)&g_Y3h[ev.x * 256 + lane * 8];
                float2 y00 = __half22float2(y.a), y01 = __half22float2(y.b);
                float2 y10 = __half22float2(y.c), y11 = __half22float2(y.d);
                P0.x += v * y00.x; P0.y += v * y00.y; P0.z += v * y01.x; P0.w += v * y01.y;
                P1.x += v * y10.x; P1.y += v * y10.y; P1.z += v * y11.x; P1.w += v * y11.y;
            }
            a0.x += c0 * P0.x; a0.y += c0 * P0.y; a0.z += c0 * P0.z; a0.w += c0 * P0.w;
            a1.x += c1 * P1.x; a1.y += c1 * P1.y; a1.z += c1 * P1.z; a1.w += c1 * P1.w;
        }
        smf[w][0][lane] = a0;
        smf[w][1][lane] = a1;
        __syncthreads();
        if (q == 0) {
            float4 v0 = smf[w][0][lane], v1 = smf[w][1][lane];
#pragma unroll
            for (int ww = 1; ww < 4; ww++) {
                float4 q0 = smf[w + ww][0][lane], q1 = smf[w + ww][1][lane];
                v0.x += q0.x; v0.y += q0.y; v0.z += q0.z; v0.w += q0.w;
                v1.x += q1.x; v1.y += q1.y; v1.z += q1.z; v1.w += q1.w;
            }
            H8 o;
            o.a = __floats2half2_rn(v0.x, v0.y);
            o.b = __floats2half2_rn(v0.z, v0.w);
            o.c = __floats2half2_rn(v1.x, v1.y);
            o.d = __floats2half2_rn(v1.z, v1.w);
            *(H8*)&g_Y2h[row * 256 + lane * 8] = o;
        }
    } else {
        // u (into g_s2u.zw)
        int r = (b - 2048) * 8 + w;
        float acc0 = 0.f, acc1 = 0.f;
#pragma unroll
        for (int j = 0; j < TT; j++) {
            float f0 = g_f2[j], f1 = g_f2[TT + j];
            int s = g_rowptr[j * (NN + 1) + r], e = g_rowptr[j * (NN + 1) + r + 1];
            const int2* ep = g_edge + j * EE;
            float p0 = 0.f, p1 = 0.f;
            for (int k = s + lane; k < e; k += 32) {
                int2 ev = ep[k];
                float v = __int_as_float(ev.y);
                float2 t3 = g_t3[ev.x];
                p0 += v * t3.x;
                p1 += v * t3.y;
            }
            acc0 += f0 * p0;
            acc1 += f1 * p1;
        }
#pragma unroll
        for (int off = 16; off > 0; off >>= 1) {
            acc0 += __shfl_down_sync(~0u, acc0, off);
            acc1 += __shfl_down_sync(~0u, acc1, off);
        }
        if (lane == 0) *(float2*)((float*)&g_s2u[r] + 2) = make_float2(acc0, acc1);  // writes .z, .w
    }
}

// ---------------- launch 6: stageC + final linear. 2 targets/block, 4 warps/target ----------------
__global__ void __launch_bounds__(256) stageC_k(const int* __restrict__ target,
                                                const float* __restrict__ gcn_b,
                                                const float* __restrict__ lin_w,
                                                const float* __restrict__ lin_b,
                                                float* __restrict__ out) {
    __shared__ float4 smf[8][2][33];
    __shared__ float smd[8][4];
    __shared__ float xts[2][CC * WOUT];
    int b = blockIdx.x;
    int tid = threadIdx.x, w = tid >> 5, lane = tid & 31;
    int tloc = w >> 2, q = w & 3;
    int t = b * 2 + tloc;
    int row = target[t];
    float4 a0 = make_float4(0, 0, 0, 0), a1 = make_float4(0, 0, 0, 0);
    float d10 = 0.f, d11 = 0.f, d20 = 0.f, d21 = 0.f;
#pragma unroll
    for (int j = 0; j < TT; j++) {
        float c0 = g_f1[j], c1 = g_f1[TT + j];
        int s = g_rowptr[j * (NN + 1) + row], e = g_rowptr[j * (NN + 1) + row + 1];
        int len = e - s;
        int qs = s + ((len * q) >> 2), qe = s + ((len * (q + 1)) >> 2);
        const int2* ep = g_edge + j * EE;
        float4 P0 = make_float4(0, 0, 0, 0), P1 = make_float4(0, 0, 0, 0);
        float pd10 = 0.f, pd11 = 0.f, pd20 = 0.f, pd21 = 0.f;
#pragma unroll 4
        for (int k = qs; k < qe; k++) {
            int2 ev = ep[k];
            int d = ev.x;
            float v = __int_as_float(ev.y);
            H8 y = *(const H8*)&g_Y2h[d * 256 + lane * 8];
            float2 y00 = __half22float2(y.a), y01 = __half22float2(y.b);
            float2 y10 = __half22float2(y.c), y11 = __half22float2(y.d);
            P0.x += v * y00.x; P0.y += v * y00.y; P0.z += v * y01.x; P0.w += v * y01.y;
            P1.x += v * y10.x; P1.y += v * y10.y; P1.z += v * y11.x; P1.w += v * y11.y;
            float4 su = g_s2u[d];
            pd10 += v * su.x; pd11 += v * su.y;
            pd20 += v * su.z; pd21 += v * su.w;
        }
        a0.x += c0 * P0.x; a0.y += c0 * P0.y; a0.z += c0 * P0.z; a0.w += c0 * P0.w;
        a1.x += c1 * P1.x; a1.y += c1 * P1.y; a1.z += c1 * P1.z; a1.w += c1 * P1.w;
        d10 += c0 * pd10; d11 += c1 * pd11;
        d20 += c0 * pd20; d21 += c1 * pd21;
    }
    smf[w][0][lane] = a0;
    smf[w][1][lane] = a1;
    // degree terms are warp-uniform: lane 0's copy is the full per-warp partial.
    if (lane == 0) { smd[w][0] = d10; smd[w][1] = d11; smd[w][2] = d20; smd[w][3] = d21; }
    __syncthreads();
    if (q == 0) {
        float4 v0 = smf[w][0][lane], v1 = smf[w][1][lane];
        float D10 = smd[w][0], D11 = smd[w][1], D20 = smd[w][2], D21 = smd[w][3];
#pragma unroll
        for (int ww = 1; ww < 4; ww++) {
            float4 q0 = smf[w + ww][0][lane], q1 = smf[w + ww][1][lane];
            v0.x += q0.x; v0.y += q0.y; v0.z += q0.z; v0.w += q0.w;
            v1.x += q1.x; v1.y += q1.y; v1.z += q1.z; v1.w += q1.w;
            D10 += smd[w + ww][0]; D11 += smd[w + ww][1];
            D20 += smd[w + ww][2]; D21 += smd[w + ww][3];
        }
        float i10 = (D10 == 0.f) ? 0.f : 1.f / D10;
        float dg0 = i10 * D20;
        float i20 = (dg0 == 0.f) ? 0.f : 1.f / dg0;
        float sc0 = i10 * i20;
        float i11 = (D11 == 0.f) ? 0.f : 1.f / D11;
        float dg1 = i11 * D21;
        float i21 = (dg1 == 0.f) ? 0.f : 1.f / dg1;
        float sc1 = i11 * i21;
        float4 bb = *(const float4*)&gcn_b[lane * 4];
        xts[tloc][0 * WOUT + lane * 4 + 0] = fmaxf(sc0 * v0.x + bb.x, 0.f);
        xts[tloc][0 * WOUT + lane * 4 + 1] = fmaxf(sc0 * v0.y + bb.y, 0.f);
        xts[tloc][0 * WOUT + lane * 4 + 2] = fmaxf(sc0 * v0.z + bb.z, 0.f);
        xts[tloc][0 * WOUT + lane * 4 + 3] = fmaxf(sc0 * v0.w + bb.w, 0.f);
        xts[tloc][1 * WOUT + lane * 4 + 0] = fmaxf(sc1 * v1.x + bb.x, 0.f);
        xts[tloc][1 * WOUT + lane * 4 + 1] = fmaxf(sc1 * v1.y + bb.y, 0.f);
        xts[tloc][1 * WOUT + lane * 4 + 2] = fmaxf(sc1 * v1.z + bb.z, 0.f);
        xts[tloc][1 * WOUT + lane * 4 + 3] = fmaxf(sc1 * v1.w + bb.w, 0.f);
    }
    __syncthreads();
    if (q == 0 && lane < NCLS) {
        float acc = lin_b[lane];
#pragma unroll 8
        for (int k = 0; k < CC * WOUT; k++)
            acc += xts[tloc][k] * lin_w[k * NCLS + lane];
        out[t * NCLS + lane] = acc;
    }
}

// ---------------- launch ----------------
extern "C" void kernel_launch(void* const* d_in, const int* in_sizes, int n_in,
                              void* d_out, int out_size) {
    const int*   edge_index = (const int*)d_in[0];
    const float* edge_value = (const float*)d_in[1];
    const float* X          = (const float*)d_in[2];
    const int*   target_x   = (const int*)d_in[3];
    const float* w_l0_c1    = (const float*)d_in[4];
    const float* w_l0_c2    = (const float*)d_in[5];
    const float* w_l1_c1    = (const float*)d_in[6];
    const float* gcn_w      = (const float*)d_in[7];
    const float* gcn_b      = (const float*)d_in[8];
    const float* lin_w      = (const float*)d_in[9];
    const float* lin_b      = (const float*)d_in[10];
    float* out = (float*)d_out;

    prep_count_k<<<128 + CNT_BLOCKS + 1, 256>>>(edge_index, X, gcn_w, w_l0_c1, w_l0_c2, w_l1_c1);
    scan_k<<<TT, 256>>>();
    scatter_k<<<SCT_BLOCKS, 256>>>(edge_index, edge_value);
    stageA_k<<<2048 + 512, 256>>>();
    stageB_k<<<2048 + 512, 256>>>();
    stageC_k<<<NT / 2, 256>>>(target_x, gcn_b, lin_w, lin_b, out);
}